// round 5
// baseline (speedup 1.0000x reference)
#include <cuda_runtime.h>
#include <math.h>
#include <stdint.h>

// Problem constants
#define N_TOK   131072      // 32 * 4096 tokens
#define DIM     64
#define KCODES  1024
#define TT      128         // tokens per CTA
#define CH      64          // codes per smem chunk
#define NCH     (KCODES / CH)   // 16
#define NB      (N_TOK / TT)    // 1024 CTAs
#define NTHREADS 256
#define XSTR    68          // padded float stride (conflict-free frag loads)

// Sound screen margin: worst-case |tf32_dist - fp32_dist| <= ~2e-4 here;
// 5e-4 adds safety.
#define MARGIN  5e-4f

// smem layout (float offsets)
#define OFF_XS   0                       // 128*68 = 8704
#define OFF_WS   8704                    // 2 * 64*68 = 8704
#define OFF_WSQ  17408                   // 1024
#define OFF_XSQ  18432                   // 128
#define OFF_FIDX 18560                   // 128 (int)
#define OFF_RED  18688                   // 256
#define SMEM_FLOATS 18944
#define SMEM_BYTES (SMEM_FLOATS * 4)

// Scratch
__device__ float g_wsq[KCODES];
__device__ int   g_counts[KCODES];
__device__ float g_part[NB];

__device__ __forceinline__ uint32_t smem_u32(const void* p) {
    uint32_t a;
    asm("{ .reg .u64 t; cvta.to.shared.u64 t, %1; cvt.u32.u64 %0, t; }"
        : "=r"(a) : "l"(p));
    return a;
}

#define CP_ASYNC16(dst_u32, src_gptr) \
    asm volatile("cp.async.ca.shared.global [%0], [%1], 16;" \
                 :: "r"(dst_u32), "l"(src_gptr) : "memory")
#define CP_COMMIT() asm volatile("cp.async.commit_group;" ::: "memory")
#define CP_WAIT0()  asm volatile("cp.async.wait_group 0;"  ::: "memory")

// mma.sync m16n8k8 tf32 (baseline PTX, family-portable)
__device__ __forceinline__ void mma_tf32(float& c0, float& c1, float& c2, float& c3,
                                         uint32_t a0, uint32_t a1, uint32_t a2, uint32_t a3,
                                         uint32_t b0, uint32_t b1) {
    asm volatile(
        "mma.sync.aligned.m16n8k8.row.col.f32.tf32.tf32.f32 "
        "{%0,%1,%2,%3}, {%4,%5,%6,%7}, {%8,%9}, {%0,%1,%2,%3};"
        : "+f"(c0), "+f"(c1), "+f"(c2), "+f"(c3)
        : "r"(a0), "r"(a1), "r"(a2), "r"(a3), "r"(b0), "r"(b1));
}

// Exact distance with R1's PROVEN accumulation order: single sequential
// fmaf chain over j = 0..63 (w_j * x_j), then fmaf(-2, dot, base).
// This reproduced the reference argmin bit-for-bit (rel_err 7.9e-8 in R1).
__device__ __forceinline__ float exact_dist(const float* __restrict__ xrow,
                                            const float* __restrict__ wrow,
                                            float base) {
    float dot = 0.f;
    #pragma unroll
    for (int j = 0; j < DIM; ++j)
        dot = fmaf(wrow[j], xrow[j], dot);
    return fmaf(-2.f, dot, base);
}

// ---------------------------------------------------------------------------
// Kernel 0: wsq + zero counts (sequential j order, as in R1)
// ---------------------------------------------------------------------------
__global__ void vq_prep(const float* __restrict__ W) {
    int k = blockIdx.x * blockDim.x + threadIdx.x;
    if (k < KCODES) {
        const float* row = W + (size_t)k * DIM;
        float s = 0.f;
        #pragma unroll
        for (int j = 0; j < DIM; ++j) s += row[j] * row[j];
        g_wsq[k]    = s;
        g_counts[k] = 0;
    }
}

// ---------------------------------------------------------------------------
// Kernel 1: tf32 HMMA screen + exact fp32 refine + quantize + loss + counts
// ---------------------------------------------------------------------------
__global__ void __launch_bounds__(NTHREADS, 2)
vq_main(const float* __restrict__ x, const float* __restrict__ W,
        float* __restrict__ out)
{
    extern __shared__ float sf[];
    float* xs    = sf + OFF_XS;     // [128][68]
    float* ws    = sf + OFF_WS;     // [2][64][68]
    float* wsq_s = sf + OFF_WSQ;    // [1024]
    float* xsq_s = sf + OFF_XSQ;    // [128]
    int*   fidx  = (int*)(sf + OFF_FIDX);
    float* red   = sf + OFF_RED;

    const int tid   = threadIdx.x;
    const int wid   = tid >> 5;
    const int lane  = tid & 31;
    const int qr    = lane >> 2;     // 0..7
    const int qc    = lane & 3;      // 0..3
    const int tbase = blockIdx.x * TT;

    const uint32_t ws_u = smem_u32(ws);

    // ---- load X tile into padded smem ----
    for (int i = tid; i < TT * 16; i += NTHREADS) {
        int t  = i >> 4;
        int c4 = (i & 15) << 2;
        float4 v = *(const float4*)(x + (size_t)(tbase + t) * DIM + c4);
        *(float4*)(xs + t * XSTR + c4) = v;
    }
    for (int i = tid; i < KCODES; i += NTHREADS) wsq_s[i] = g_wsq[i];

    // ---- prefetch W chunk 0 ----
    for (int i = tid; i < CH * 16; i += NTHREADS) {
        int r = i >> 4, c4 = (i & 15) << 2;
        CP_ASYNC16(ws_u + (uint32_t)(r * XSTR + c4) * 4,
                   W + (size_t)r * DIM + c4);
    }
    CP_COMMIT();
    __syncthreads();

    // ---- xsq per token (sequential, as R1) ----
    if (tid < TT) {
        const float* row = xs + tid * XSTR;
        float s = 0.f;
        #pragma unroll
        for (int j = 0; j < DIM; ++j) { float v = row[j]; s += v * v; }
        xsq_s[tid] = s;
    }
    __syncthreads();

    // ---- A fragments: 16 tokens per warp, K=64 ----
    const int t0 = wid * 16 + qr;
    uint32_t a[8][4];
    #pragma unroll
    for (int ki = 0; ki < 8; ++ki) {
        a[ki][0] = __float_as_uint(xs[t0 * XSTR + ki * 8 + qc]);
        a[ki][1] = __float_as_uint(xs[(t0 + 8) * XSTR + ki * 8 + qc]);
        a[ki][2] = __float_as_uint(xs[t0 * XSTR + ki * 8 + qc + 4]);
        a[ki][3] = __float_as_uint(xs[(t0 + 8) * XSTR + ki * 8 + qc + 4]);
    }
    const float xsq0 = xsq_s[t0];
    const float xsq1 = xsq_s[t0 + 8];
    const float* xrow0 = xs + t0 * XSTR;
    const float* xrow1 = xs + (t0 + 8) * XSTR;

    float bestd0 = 3.0e38f, bestd1 = 3.0e38f;   // EXACT (R1-order) distances
    int   besti0 = 0,       besti1 = 0;

    for (int c = 0; c < NCH; ++c) {
        const int b = c & 1;
        CP_WAIT0();
        __syncthreads();

        if (c + 1 < NCH) {
            const float* src = W + (size_t)(c + 1) * CH * DIM;
            const uint32_t dst0 = ws_u + (uint32_t)(((c + 1) & 1) * CH * XSTR) * 4;
            for (int i = tid; i < CH * 16; i += NTHREADS) {
                int r = i >> 4, c4 = (i & 15) << 2;
                CP_ASYNC16(dst0 + (uint32_t)(r * XSTR + c4) * 4,
                           src + (size_t)r * DIM + c4);
            }
            CP_COMMIT();
        }

        const float* wbuf = ws + b * CH * XSTR;

        #pragma unroll
        for (int tile = 0; tile < CH / 8; ++tile) {
            const float* brow = wbuf + (tile * 8 + qr) * XSTR;
            float c0 = 0.f, c1 = 0.f, c2 = 0.f, c3 = 0.f;
            #pragma unroll
            for (int ki = 0; ki < 8; ++ki) {
                uint32_t b0 = __float_as_uint(brow[ki * 8 + qc]);
                uint32_t b1 = __float_as_uint(brow[ki * 8 + qc + 4]);
                mma_tf32(c0, c1, c2, c3, a[ki][0], a[ki][1], a[ki][2], a[ki][3], b0, b1);
            }
            // screen with approx dist; refine with R1-exact when within margin
            const int lc0 = tile * 8 + 2 * qc;       // local code in chunk
            const int g0  = c * CH + lc0;
            const int g1  = g0 + 1;
            const float base00 = wsq_s[g0] + xsq0;   // fl(wsq+xsq), as reference
            const float base10 = wsq_s[g1] + xsq0;
            const float base01 = wsq_s[g0] + xsq1;
            const float base11 = wsq_s[g1] + xsq1;
            const float* w0row = wbuf + lc0 * XSTR;
            const float* w1row = w0row + XSTR;
            float apx;
            apx = fmaf(-2.f, c0, base00);
            if (apx < bestd0 + MARGIN) {
                float d = exact_dist(xrow0, w0row, base00);
                if (d < bestd0) { bestd0 = d; besti0 = g0; }
            }
            apx = fmaf(-2.f, c1, base10);
            if (apx < bestd0 + MARGIN) {
                float d = exact_dist(xrow0, w1row, base10);
                if (d < bestd0) { bestd0 = d; besti0 = g1; }
            }
            apx = fmaf(-2.f, c2, base01);
            if (apx < bestd1 + MARGIN) {
                float d = exact_dist(xrow1, w0row, base01);
                if (d < bestd1) { bestd1 = d; besti1 = g0; }
            }
            apx = fmaf(-2.f, c3, base11);
            if (apx < bestd1 + MARGIN) {
                float d = exact_dist(xrow1, w1row, base11);
                if (d < bestd1) { bestd1 = d; besti1 = g1; }
            }
        }
    }

    // ---- reduce argmin across the quad (4 threads share each token row) ----
    #pragma unroll
    for (int off = 1; off <= 2; off <<= 1) {
        float od0 = __shfl_xor_sync(0xffffffffu, bestd0, off);
        int   oi0 = __shfl_xor_sync(0xffffffffu, besti0, off);
        if (od0 < bestd0 || (od0 == bestd0 && oi0 < besti0)) { bestd0 = od0; besti0 = oi0; }
        float od1 = __shfl_xor_sync(0xffffffffu, bestd1, off);
        int   oi1 = __shfl_xor_sync(0xffffffffu, besti1, off);
        if (od1 < bestd1 || (od1 == bestd1 && oi1 < besti1)) { bestd1 = od1; besti1 = oi1; }
    }
    if (qc == 0) {
        fidx[t0]     = besti0;
        fidx[t0 + 8] = besti1;
        atomicAdd(&g_counts[besti0], 1);
        atomicAdd(&g_counts[besti1], 1);
    }
    __syncthreads();

    // ---- epilogue: quantized_st (coalesced) + loss partial ----
    float ls = 0.f;
    for (int i = tid; i < TT * 16; i += NTHREADS) {
        int t  = i >> 4;
        int c4 = (i & 15) << 2;
        int kb = fidx[t];
        float4 w4 = *(const float4*)(W + (size_t)kb * DIM + c4);
        float4 xv = *(const float4*)(xs + t * XSTR + c4);
        float4 o; float dq;
        dq = w4.x - xv.x; o.x = xv.x + dq; ls = fmaf(dq, dq, ls);
        dq = w4.y - xv.y; o.y = xv.y + dq; ls = fmaf(dq, dq, ls);
        dq = w4.z - xv.z; o.z = xv.z + dq; ls = fmaf(dq, dq, ls);
        dq = w4.w - xv.w; o.w = xv.w + dq; ls = fmaf(dq, dq, ls);
        *(float4*)(out + (size_t)(tbase + t) * DIM + c4) = o;
    }

    // deterministic fixed-order block reduce of loss
    red[tid] = ls;
    __syncthreads();
    for (int off = NTHREADS / 2; off > 0; off >>= 1) {
        if (tid < off) red[tid] += red[tid + off];
        __syncthreads();
    }
    if (tid == 0) g_part[blockIdx.x] = red[0];
}

// ---------------------------------------------------------------------------
// Kernel 2: final scalars (loss, perplexity, usage)
// ---------------------------------------------------------------------------
__global__ void vq_final(float* __restrict__ out, int out_size) {
    __shared__ float red[1024];
    __shared__ float red2[1024];
    int tid = threadIdx.x;

    red[tid] = g_part[tid];
    __syncthreads();
    for (int off = 512; off > 0; off >>= 1) {
        if (tid < off) red[tid] += red[tid + off];
        __syncthreads();
    }
    float sse = red[0];
    __syncthreads();

    int c  = g_counts[tid];
    float p = (float)c / (float)N_TOK;
    red[tid]  = p * logf(p + 1e-10f);
    red2[tid] = (c >= 1) ? 1.f : 0.f;
    __syncthreads();
    for (int off = 512; off > 0; off >>= 1) {
        if (tid < off) { red[tid] += red[tid + off]; red2[tid] += red2[tid + off]; }
        __syncthreads();
    }
    if (tid == 0 && out_size >= N_TOK * DIM + 3) {
        float mse = sse / (float)(N_TOK * DIM);
        out[N_TOK * DIM + 0] = mse + 2.0f * mse;   // q_latent + COMMITMENT_COST*e_latent
        out[N_TOK * DIM + 1] = expf(-red[0]);
        out[N_TOK * DIM + 2] = red2[0];
    }
}

// ---------------------------------------------------------------------------
extern "C" void kernel_launch(void* const* d_in, const int* in_sizes, int n_in,
                              void* d_out, int out_size) {
    const float* x = (const float*)d_in[0];   // [32,4096,64] f32
    const float* W = (const float*)d_in[1];   // [1024,64] f32
    float* out = (float*)d_out;

    cudaFuncSetAttribute(vq_main, cudaFuncAttributeMaxDynamicSharedMemorySize,
                         SMEM_BYTES);

    vq_prep<<<KCODES / 256, 256>>>(W);
    vq_main<<<NB, NTHREADS, SMEM_BYTES>>>(x, W, out);
    vq_final<<<1, 1024>>>(out, out_size);
}

// round 6
// speedup vs baseline: 1.2491x; 1.2491x over previous
#include <cuda_runtime.h>
#include <math.h>
#include <stdint.h>

// Problem constants
#define N_TOK   131072      // 32 * 4096 tokens
#define DIM     64
#define KCODES  1024
#define TT      128         // tokens per CTA
#define CH      64          // codes per smem chunk
#define NCH     (KCODES / CH)   // 16
#define NB      (N_TOK / TT)    // 1024 CTAs
#define NTHREADS 256
#define XSTR    68          // padded float stride (conflict-free frag loads)

// Sound screen margin: must exceed 2 * worst-case |tf32_dist - fp32_dist|
// (<= 2*1.9e-4 = 3.8e-4 for this data). 1e-3 is safely above.
#define MARGIN  1e-3f

#define QCAP    4096        // candidate queue capacity (entries)

// smem layout (float offsets)
#define OFF_XS     0                     // 128*68 = 8704
#define OFF_WS     8704                  // 2 * 64*68 = 8704
#define OFF_WSQ    17408                 // 1024
#define OFF_XSQ    18432                 // 128
#define OFF_BEST   18560                 // 128 u64 = 256 floats (8B aligned)
#define OFF_QCNT   18816                 // 1 (+3 pad)
#define OFF_QUEUE  18820                 // 4096 u32
#define OFF_FIDX   22916                 // 128 int
#define OFF_RED    23044                 // 256
#define SMEM_FLOATS 23300
#define SMEM_BYTES (SMEM_FLOATS * 4)

// Scratch
__device__ float g_wsq[KCODES];
__device__ int   g_counts[KCODES];
__device__ float g_part[NB];

__device__ __forceinline__ uint32_t smem_u32(const void* p) {
    uint32_t a;
    asm("{ .reg .u64 t; cvta.to.shared.u64 t, %1; cvt.u32.u64 %0, t; }"
        : "=r"(a) : "l"(p));
    return a;
}

#define CP_ASYNC16(dst_u32, src_gptr) \
    asm volatile("cp.async.ca.shared.global [%0], [%1], 16;" \
                 :: "r"(dst_u32), "l"(src_gptr) : "memory")
#define CP_COMMIT() asm volatile("cp.async.commit_group;" ::: "memory")
#define CP_WAIT0()  asm volatile("cp.async.wait_group 0;"  ::: "memory")

// mma.sync m16n8k8 tf32 (baseline PTX, family-portable)
__device__ __forceinline__ void mma_tf32(float& c0, float& c1, float& c2, float& c3,
                                         uint32_t a0, uint32_t a1, uint32_t a2, uint32_t a3,
                                         uint32_t b0, uint32_t b1) {
    asm volatile(
        "mma.sync.aligned.m16n8k8.row.col.f32.tf32.tf32.f32 "
        "{%0,%1,%2,%3}, {%4,%5,%6,%7}, {%8,%9}, {%0,%1,%2,%3};"
        : "+f"(c0), "+f"(c1), "+f"(c2), "+f"(c3)
        : "r"(a0), "r"(a1), "r"(a2), "r"(a3), "r"(b0), "r"(b1));
}

// Exact distance with R1's PROVEN accumulation: single sequential fmaf
// chain over j = 0..63, then fmaf(-2, dot, base). (Matched reference
// argmin bit-for-bit in R1: rel_err 7.9e-8.)
__device__ __forceinline__ float exact_dist(const float* __restrict__ xrow,
                                            const float* __restrict__ wrow,
                                            float base) {
    float dot = 0.f;
    #pragma unroll
    for (int j = 0; j < DIM; ++j)
        dot = fmaf(wrow[j], xrow[j], dot);
    return fmaf(-2.f, dot, base);
}

// Warp-aggregated queue append. cond per-lane; uniform control flow required.
__device__ __forceinline__ void queue_append(
    int cond, uint32_t entry, int* qcount, uint32_t* queue,
    const float* xrow, const float* wrow, float base, uint32_t gcode,
    unsigned long long* bestp)
{
    unsigned m = __ballot_sync(0xffffffffu, cond);
    if (cond) {
        int lane   = threadIdx.x & 31;
        int leader = __ffs(m) - 1;
        int rank   = __popc(m & ((1u << lane) - 1u));
        int basep  = 0;
        if (lane == leader) basep = atomicAdd(qcount, __popc(m));
        basep = __shfl_sync(m, basep, leader);
        int slot = basep + rank;
        if (slot < QCAP) {
            queue[slot] = entry;
        } else {
            // overflow fallback (statistically never): refine inline
            float d = exact_dist(xrow, wrow, base);
            unsigned long long key =
                ((unsigned long long)__float_as_uint(d) << 32) | gcode;
            atomicMin(bestp, key);
        }
    }
}

// ---------------------------------------------------------------------------
// Kernel 0: wsq + zero counts (sequential j order, as in R1)
// ---------------------------------------------------------------------------
__global__ void vq_prep(const float* __restrict__ W) {
    int k = blockIdx.x * blockDim.x + threadIdx.x;
    if (k < KCODES) {
        const float* row = W + (size_t)k * DIM;
        float s = 0.f;
        #pragma unroll
        for (int j = 0; j < DIM; ++j) s += row[j] * row[j];
        g_wsq[k]    = s;
        g_counts[k] = 0;
    }
}

// ---------------------------------------------------------------------------
// Kernel 1: tf32 HMMA screen (branchless) + queued exact refine
// ---------------------------------------------------------------------------
__global__ void __launch_bounds__(NTHREADS, 2)
vq_main(const float* __restrict__ x, const float* __restrict__ W,
        float* __restrict__ out)
{
    extern __shared__ float sf[];
    float* xs    = sf + OFF_XS;     // [128][68]
    float* ws    = sf + OFF_WS;     // [2][64][68]
    float* wsq_s = sf + OFF_WSQ;    // [1024]
    float* xsq_s = sf + OFF_XSQ;    // [128]
    unsigned long long* best = (unsigned long long*)(sf + OFF_BEST);  // [128]
    int*      qcount = (int*)(sf + OFF_QCNT);
    uint32_t* queue  = (uint32_t*)(sf + OFF_QUEUE);
    int*      fidx   = (int*)(sf + OFF_FIDX);
    float*    red    = sf + OFF_RED;

    const int tid   = threadIdx.x;
    const int wid   = tid >> 5;
    const int lane  = tid & 31;
    const int qr    = lane >> 2;     // 0..7
    const int qc    = lane & 3;      // 0..3
    const int tbase = blockIdx.x * TT;

    const uint32_t ws_u = smem_u32(ws);

    // ---- init ----
    if (tid == 0) *qcount = 0;
    if (tid < TT) best[tid] = 0xFFFFFFFFFFFFFFFFull;

    // ---- load X tile into padded smem ----
    for (int i = tid; i < TT * 16; i += NTHREADS) {
        int t  = i >> 4;
        int c4 = (i & 15) << 2;
        float4 v = *(const float4*)(x + (size_t)(tbase + t) * DIM + c4);
        *(float4*)(xs + t * XSTR + c4) = v;
    }
    for (int i = tid; i < KCODES; i += NTHREADS) wsq_s[i] = g_wsq[i];

    // ---- prefetch W chunk 0 ----
    for (int i = tid; i < CH * 16; i += NTHREADS) {
        int r = i >> 4, c4 = (i & 15) << 2;
        CP_ASYNC16(ws_u + (uint32_t)(r * XSTR + c4) * 4,
                   W + (size_t)r * DIM + c4);
    }
    CP_COMMIT();
    __syncthreads();

    // ---- xsq per token (sequential, as R1) ----
    if (tid < TT) {
        const float* row = xs + tid * XSTR;
        float s = 0.f;
        #pragma unroll
        for (int j = 0; j < DIM; ++j) { float v = row[j]; s += v * v; }
        xsq_s[tid] = s;
    }
    __syncthreads();

    // ---- A fragments: 16 tokens per warp, K=64 ----
    const int t0 = wid * 16 + qr;
    uint32_t a[8][4];
    #pragma unroll
    for (int ki = 0; ki < 8; ++ki) {
        a[ki][0] = __float_as_uint(xs[t0 * XSTR + ki * 8 + qc]);
        a[ki][1] = __float_as_uint(xs[(t0 + 8) * XSTR + ki * 8 + qc]);
        a[ki][2] = __float_as_uint(xs[t0 * XSTR + ki * 8 + qc + 4]);
        a[ki][3] = __float_as_uint(xs[(t0 + 8) * XSTR + ki * 8 + qc + 4]);
    }
    const float xsq0 = xsq_s[t0];
    const float xsq1 = xsq_s[t0 + 8];
    const float* xrow0 = xs + t0 * XSTR;
    const float* xrow1 = xs + (t0 + 8) * XSTR;

    float rlb0 = 3.0e38f, rlb1 = 3.0e38f;   // running local APPROX minima

    for (int c = 0; c < NCH; ++c) {
        const int b = c & 1;
        CP_WAIT0();
        __syncthreads();                 // syncA: chunk c in buf b; qcount reset

        if (c + 1 < NCH) {               // prefetch next chunk into other buffer
            const float* src = W + (size_t)(c + 1) * CH * DIM;
            const uint32_t dst0 = ws_u + (uint32_t)(((c + 1) & 1) * CH * XSTR) * 4;
            for (int i = tid; i < CH * 16; i += NTHREADS) {
                int r = i >> 4, c4 = (i & 15) << 2;
                CP_ASYNC16(dst0 + (uint32_t)(r * XSTR + c4) * 4,
                           src + (size_t)r * DIM + c4);
            }
            CP_COMMIT();
        }

        const float* wbuf = ws + b * CH * XSTR;

        #pragma unroll
        for (int tile = 0; tile < CH / 8; ++tile) {
            const float* brow = wbuf + (tile * 8 + qr) * XSTR;
            float c0 = 0.f, c1 = 0.f, c2 = 0.f, c3 = 0.f;
            #pragma unroll
            for (int ki = 0; ki < 8; ++ki) {
                uint32_t b0 = __float_as_uint(brow[ki * 8 + qc]);
                uint32_t b1 = __float_as_uint(brow[ki * 8 + qc + 4]);
                mma_tf32(c0, c1, c2, c3, a[ki][0], a[ki][1], a[ki][2], a[ki][3], b0, b1);
            }
            const int lc0 = tile * 8 + 2 * qc;       // local code in chunk
            const int g0  = c * CH + lc0;
            const int g1  = g0 + 1;
            const float base00 = wsq_s[g0] + xsq0;
            const float base10 = wsq_s[g1] + xsq0;
            const float base01 = wsq_s[g0] + xsq1;
            const float base11 = wsq_s[g1] + xsq1;
            float a00 = fmaf(-2.f, c0, base00);
            float a10 = fmaf(-2.f, c1, base10);
            float a01 = fmaf(-2.f, c2, base01);
            float a11 = fmaf(-2.f, c3, base11);

            // ballot-append candidates (vs pre-update running local min)
            queue_append(a00 < rlb0 + MARGIN, (uint32_t)((t0 << 8) | lc0),
                         qcount, queue, xrow0, wbuf + lc0 * XSTR, base00,
                         (uint32_t)g0, &best[t0]);
            queue_append(a10 < rlb0 + MARGIN, (uint32_t)((t0 << 8) | (lc0 + 1)),
                         qcount, queue, xrow0, wbuf + (lc0 + 1) * XSTR, base10,
                         (uint32_t)g1, &best[t0]);
            queue_append(a01 < rlb1 + MARGIN, (uint32_t)(((t0 + 8) << 8) | lc0),
                         qcount, queue, xrow1, wbuf + lc0 * XSTR, base01,
                         (uint32_t)g0, &best[t0 + 8]);
            queue_append(a11 < rlb1 + MARGIN, (uint32_t)(((t0 + 8) << 8) | (lc0 + 1)),
                         qcount, queue, xrow1, wbuf + (lc0 + 1) * XSTR, base11,
                         (uint32_t)g1, &best[t0 + 8]);

            // branchless running-min update
            rlb0 = fminf(rlb0, fminf(a00, a10));
            rlb1 = fminf(rlb1, fminf(a01, a11));
        }

        __syncthreads();                 // syncB: appends visible

        // ---- cooperative exact refine of this chunk's candidates ----
        const int n = *qcount;
        const int nq = n < QCAP ? n : QCAP;
        for (int i = tid; i < nq; i += NTHREADS) {
            uint32_t e = queue[i];
            int t  = (int)(e >> 8);
            int lc = (int)(e & 255);
            float base = wsq_s[c * CH + lc] + xsq_s[t];
            float d = exact_dist(xs + t * XSTR, wbuf + lc * XSTR, base);
            unsigned long long key =
                ((unsigned long long)__float_as_uint(d) << 32)
                | (uint32_t)(c * CH + lc);
            atomicMin(&best[t], key);
        }

        __syncthreads();                 // syncC: refine done
        if (tid == 0) *qcount = 0;       // ordered before next syncA
    }

    __syncthreads();
    if (tid < TT) {
        int bi = (int)(best[tid] & 0xFFFFFFFFull);
        fidx[tid] = bi;
        atomicAdd(&g_counts[bi], 1);
    }
    __syncthreads();

    // ---- epilogue: quantized_st (coalesced) + loss partial ----
    float ls = 0.f;
    for (int i = tid; i < TT * 16; i += NTHREADS) {
        int t  = i >> 4;
        int c4 = (i & 15) << 2;
        int kb = fidx[t];
        float4 w4 = *(const float4*)(W + (size_t)kb * DIM + c4);
        float4 xv = *(const float4*)(xs + t * XSTR + c4);
        float4 o; float dq;
        dq = w4.x - xv.x; o.x = xv.x + dq; ls = fmaf(dq, dq, ls);
        dq = w4.y - xv.y; o.y = xv.y + dq; ls = fmaf(dq, dq, ls);
        dq = w4.z - xv.z; o.z = xv.z + dq; ls = fmaf(dq, dq, ls);
        dq = w4.w - xv.w; o.w = xv.w + dq; ls = fmaf(dq, dq, ls);
        *(float4*)(out + (size_t)(tbase + t) * DIM + c4) = o;
    }

    // deterministic fixed-order block reduce of loss
    red[tid] = ls;
    __syncthreads();
    for (int off = NTHREADS / 2; off > 0; off >>= 1) {
        if (tid < off) red[tid] += red[tid + off];
        __syncthreads();
    }
    if (tid == 0) g_part[blockIdx.x] = red[0];
}

// ---------------------------------------------------------------------------
// Kernel 2: final scalars (loss, perplexity, usage)
// ---------------------------------------------------------------------------
__global__ void vq_final(float* __restrict__ out, int out_size) {
    __shared__ float red[1024];
    __shared__ float red2[1024];
    int tid = threadIdx.x;

    red[tid] = g_part[tid];
    __syncthreads();
    for (int off = 512; off > 0; off >>= 1) {
        if (tid < off) red[tid] += red[tid + off];
        __syncthreads();
    }
    float sse = red[0];
    __syncthreads();

    int c  = g_counts[tid];
    float p = (float)c / (float)N_TOK;
    red[tid]  = p * logf(p + 1e-10f);
    red2[tid] = (c >= 1) ? 1.f : 0.f;
    __syncthreads();
    for (int off = 512; off > 0; off >>= 1) {
        if (tid < off) { red[tid] += red[tid + off]; red2[tid] += red2[tid + off]; }
        __syncthreads();
    }
    if (tid == 0 && out_size >= N_TOK * DIM + 3) {
        float mse = sse / (float)(N_TOK * DIM);
        out[N_TOK * DIM + 0] = mse + 2.0f * mse;   // q_latent + COMMITMENT_COST*e_latent
        out[N_TOK * DIM + 1] = expf(-red[0]);
        out[N_TOK * DIM + 2] = red2[0];
    }
}

// ---------------------------------------------------------------------------
extern "C" void kernel_launch(void* const* d_in, const int* in_sizes, int n_in,
                              void* d_out, int out_size) {
    const float* x = (const float*)d_in[0];   // [32,4096,64] f32
    const float* W = (const float*)d_in[1];   // [1024,64] f32
    float* out = (float*)d_out;

    cudaFuncSetAttribute(vq_main, cudaFuncAttributeMaxDynamicSharedMemorySize,
                         SMEM_BYTES);

    vq_prep<<<8, 128>>>(W);
    vq_main<<<NB, NTHREADS, SMEM_BYTES>>>(x, W, out);
    vq_final<<<1, 1024>>>(out, out_size);
}